// round 14
// baseline (speedup 1.0000x reference)
#include <cuda_runtime.h>

// FIR: out[b,t,c] = sum_{i=0..15} w[i,c] * x[b, t-15+i, c]   (causal, zero-padded)
// x: [B=64, T=2048, C=32] fp32, w: [16, 32] fp32, out: [B, T, C] fp32.
//
// Round 14: smem tile + fma2 + streaming accs + small blocks.
//  - Block = (batch, 64-timestep tile), 128 threads, 10KB smem (tile + 15-row
//    halo; halo zero-filled for the first tile -> uniform compute, no edge code).
//  - Window reads are 23 conflict-free LDS.64 (29 cyc) instead of L2-latency
//    LDGs; only ~5 staging LDG.128 per thread stay long-scoreboard.
//  - Streaming 8 packed accumulators, first touch via mul2; 64-reg cap.

#define B_SZ 64
#define T_SZ 2048
#define C_SZ 32
#define F_SZ 16
#define GRP  8
#define HALO (F_SZ - 1)                 // 15
#define WIN  (GRP + HALO)               // 23
#define NPAIR (C_SZ / 2)                // 16
#define TILE_T 64
#define THREADS 128                     // 8 time-groups x 16 channel pairs

#define SMEM_T (TILE_T + HALO)          // 79 rows
#define SMEM_VEC (SMEM_T * C_SZ / 4)    // 632 float4
#define ZERO_VEC (HALO * C_SZ / 4)      // 120 leading zero-vectors when t0==0

typedef unsigned long long u64;

__device__ __forceinline__ u64 fma2(u64 a, u64 b, u64 c) {
    u64 d;
    asm("fma.rn.f32x2 %0, %1, %2, %3;" : "=l"(d) : "l"(a), "l"(b), "l"(c));
    return d;
}
__device__ __forceinline__ u64 mul2(u64 a, u64 b) {
    u64 d;
    asm("mul.rn.f32x2 %0, %1, %2;" : "=l"(d) : "l"(a), "l"(b));
    return d;
}

__global__ __launch_bounds__(THREADS, 8)   // cap 64 regs/thread
void fir_kernel(const float* __restrict__ x,
                const float* __restrict__ w,
                float* __restrict__ out) {
    __shared__ float4 tile[SMEM_VEC];

    const int tid = threadIdx.x;
    const int b   = blockIdx.x;
    const int t0  = blockIdx.y * TILE_T;
    const int cp  = tid & (NPAIR - 1);

    // taps first so their LDGs overlap the staging loads
    u64 wp[F_SZ];
    const u64* wpr = (const u64*)w;               // [16][16] pairs
#pragma unroll
    for (int i = 0; i < F_SZ; i++) wp[i] = wpr[i * NPAIR + cp];

    // ---- stage gmem rows [t0-15 .. t0+63] x [0..31] into smem ----
    const long gbase = ((long)b * T_SZ + t0 - HALO) * C_SZ;   // float offset
    const float4* gx = (const float4*)(x + gbase);

    if (t0 != 0) {
#pragma unroll
        for (int k = 0; k < 5; k++) {
            const int v = tid + k * THREADS;
            if (v < SMEM_VEC) tile[v] = gx[v];
        }
    } else {
#pragma unroll
        for (int k = 0; k < 5; k++) {
            const int v = tid + k * THREADS;
            if (v < SMEM_VEC)
                tile[v] = (v < ZERO_VEC) ? make_float4(0.f, 0.f, 0.f, 0.f)
                                         : gx[v];
        }
    }
    __syncthreads();

    // ---- compute: thread = channel pair cp, tile rows u0..u0+7 ----
    const int u0 = (tid >> 4) * GRP;              // 0,8,...,56 (local row)
    const u64* smp = (const u64*)tile;            // packed pairs, 16 per row

    u64 acc[GRP];
#pragma unroll
    for (int j = 0; j < WIN; j++) {
        const u64 xv = smp[(u0 + j) * NPAIR + cp];   // LDS.64, conflict-free
        const int ulo = (j - HALO < 0) ? 0 : j - HALO;
        const int uhi = (j < GRP - 1) ? j : GRP - 1;
#pragma unroll
        for (int u = ulo; u <= uhi; u++)
            acc[u] = (j == u) ? mul2(wp[j - u], xv)
                              : fma2(wp[j - u], xv, acc[u]);
    }

    u64* op = (u64*)out + ((long)b * T_SZ + t0 + u0) * NPAIR + cp;
#pragma unroll
    for (int u = 0; u < GRP; u++)
        op[u * NPAIR] = acc[u];
}

extern "C" void kernel_launch(void* const* d_in, const int* in_sizes, int n_in,
                              void* d_out, int out_size) {
    const float* x = (const float*)d_in[0];   // [64, 2048, 32]
    const float* w = (const float*)d_in[1];   // [16, 32]
    float* out = (float*)d_out;

    dim3 grid(B_SZ, T_SZ / TILE_T);           // (64, 32) = 2048 blocks
    fir_kernel<<<grid, THREADS>>>(x, w, out);
}